// round 12
// baseline (speedup 1.0000x reference)
#include <cuda_runtime.h>
#include <cuda_fp16.h>
#include <math.h>
#include <stdint.h>

// ---------------------------------------------------------------------------
// WanSelfAttention: B=1, L=5000, dim=1536, heads=12, head_dim=128, fp32 I/O.
// R11 (= R9 fixed): fp16x3 tensor cores. GEMMs: ldmatrix + cp.async.
// Attention FA2-style: warp-owned score rows, register softmax, S fragments
// repacked directly into PV A-operands. 128q x 64k tiles, 8 warps.
// ---------------------------------------------------------------------------

#define MAX_L 5120
#define DIMV  1536
#define NPAIR 768            // DIMV/2
#define VROW  (MAX_L / 2)    // token-pairs per d row

// fp32 intermediates
__device__ float g_Q[MAX_L * DIMV];
__device__ float g_K[MAX_L * DIMV];
__device__ float g_V[MAX_L * DIMV];
// packed fp16 hi/lo pair buffers
__device__ uint32_t g_Xp[2][MAX_L * NPAIR];        // x: [token][kpair]
__device__ uint32_t g_Wp[8][NPAIR * DIMV];         // W transposed: [n][kpair]
__device__ uint32_t g_Qp[2][MAX_L * NPAIR];        // [token][dpair]
__device__ uint32_t g_Kp[2][MAX_L * NPAIR];
__device__ uint32_t g_Vp[2][DIMV * VROW];          // V transposed: [d][tokenpair]
__device__ uint32_t g_Op[2][MAX_L * NPAIR];

// ---------------- helpers ----------------
__device__ __forceinline__ void cp16(void* smem_dst, const void* gsrc) {
    uint32_t s = (uint32_t)__cvta_generic_to_shared(smem_dst);
    asm volatile("cp.async.cg.shared.global [%0], [%1], 16;\n" :: "r"(s), "l"(gsrc));
}
#define CP_COMMIT() asm volatile("cp.async.commit_group;\n" ::: "memory")
#define CP_WAIT(n)  asm volatile("cp.async.wait_group %0;\n" :: "n"(n) : "memory")

__device__ __forceinline__ void ldsm4(uint32_t* r, const uint32_t* p) {
    uint32_t a = (uint32_t)__cvta_generic_to_shared(p);
    asm volatile("ldmatrix.sync.aligned.m8n8.x4.shared.b16 {%0,%1,%2,%3}, [%4];"
        : "=r"(r[0]), "=r"(r[1]), "=r"(r[2]), "=r"(r[3]) : "r"(a));
}

__device__ __forceinline__ void split2(float x, float y, uint32_t& hi, uint32_t& lo) {
    __half2 h = __floats2half2_rn(x, y);
    float2 hf = __half22float2(h);
    __half2 l = __floats2half2_rn(x - hf.x, y - hf.y);
    hi = *reinterpret_cast<uint32_t*>(&h);
    lo = *reinterpret_cast<uint32_t*>(&l);
}

__device__ __forceinline__ void mma_f16(float* c, const uint32_t* a, const uint32_t* b) {
    asm volatile(
        "mma.sync.aligned.m16n8k16.row.col.f32.f16.f16.f32 "
        "{%0,%1,%2,%3}, {%4,%5,%6,%7}, {%8,%9}, {%0,%1,%2,%3};\n"
        : "+f"(c[0]), "+f"(c[1]), "+f"(c[2]), "+f"(c[3])
        : "r"(a[0]), "r"(a[1]), "r"(a[2]), "r"(a[3]), "r"(b[0]), "r"(b[1]));
}
__device__ __forceinline__ void mma3(float* c,
                                     const uint32_t* ah, const uint32_t* al,
                                     const uint32_t* bh, const uint32_t* bl) {
    mma_f16(c, al, bh);
    mma_f16(c, ah, bl);
    mma_f16(c, ah, bh);
}

// ---------------------------------------------------------------------------
// Prep kernels
// ---------------------------------------------------------------------------
__global__ void split_rows_kernel(const float* __restrict__ X,
                                  uint32_t* __restrict__ hi, uint32_t* __restrict__ lo,
                                  int npairs)
{
    int i = blockIdx.x * 256 + threadIdx.x;
    if (i >= npairs) return;
    float2 v = reinterpret_cast<const float2*>(X)[i];
    uint32_t h, l; split2(v.x, v.y, h, l);
    hi[i] = h; lo[i] = l;
}

__global__ void split_trans_kernel(const float* __restrict__ X,
                                   uint32_t* __restrict__ hi, uint32_t* __restrict__ lo,
                                   int R, int C, int RPstride, float scale)
{
    __shared__ float tile[64][33];
    int r0 = blockIdx.y * 64, c0 = blockIdx.x * 32;
    int tx = threadIdx.x, ty = threadIdx.y;   // 32 x 8
#pragma unroll
    for (int i = 0; i < 8; i++) {
        int r = r0 + ty + i * 8;
        float v = 0.f;
        if (r < R && c0 + tx < C) v = X[(size_t)r * C + c0 + tx] * scale;
        tile[ty + i * 8][tx] = v;
    }
    __syncthreads();
#pragma unroll
    for (int i = 0; i < 4; i++) {
        int cy = ty + i * 8;
        int cc = c0 + cy;
        int rp = (r0 >> 1) + tx;
        if (cc < C && 2 * rp < R) {
            uint32_t h, l;
            split2(tile[2 * tx][cy], tile[2 * tx + 1][cy], h, l);
            hi[(size_t)cc * RPstride + rp] = h;
            lo[(size_t)cc * RPstride + rp] = l;
        }
    }
}

// ---------------------------------------------------------------------------
// GEMM fp16x3 (R7 design): C[M,N] = (Ap @ Bp^T) * outScale + bias
// ---------------------------------------------------------------------------
#define G_ST 20
__global__ void __launch_bounds__(256)
gemm_f16x3_kernel(const uint32_t* __restrict__ Ahi, const uint32_t* __restrict__ Alo,
                  const uint32_t* __restrict__ Bhi, const uint32_t* __restrict__ Blo,
                  const float* __restrict__ bias, float* __restrict__ C,
                  int M, int N, int Kp, float outScale)
{
    const int TBUF = 128 * G_ST;
    extern __shared__ uint32_t sh[];
    uint32_t* Ah = sh;
    uint32_t* Al = Ah + 2 * TBUF;
    uint32_t* Bh = Al + 2 * TBUF;
    uint32_t* Bl = Bh + 2 * TBUF;

    int tid = threadIdx.x;
    int lane = tid & 31, warp = tid >> 5;
    int wm = warp >> 2, wn = warp & 3;
    int g = lane >> 2, tg = lane & 3;
    int row0 = blockIdx.x * 128, col0 = blockIdx.y * 128;

    int arow  = (lane & 7) + ((lane & 8) ? 8 : 0);
    int apair = (lane & 16) ? 4 : 0;
    int brow  = (lane & 7) + ((lane & 16) ? 8 : 0);
    int bpair = (lane & 8) ? 4 : 0;

    float acc[4][4][4];
#pragma unroll
    for (int mt = 0; mt < 4; mt++)
#pragma unroll
        for (int nt = 0; nt < 4; nt++)
#pragma unroll
            for (int r = 0; r < 4; r++) acc[mt][nt][r] = 0.f;

    auto issue = [&](int ktp, int buf) {
#pragma unroll
        for (int i = 0; i < 2; i++) {
            int idx = tid + i * 256;
            int r = idx >> 2, pc = (idx & 3) << 2;
            int gr = row0 + r; if (gr >= M) gr = M - 1;
            size_t go = (size_t)gr * Kp + ktp + pc;
            cp16(Ah + buf * TBUF + r * G_ST + pc, Ahi + go);
            cp16(Al + buf * TBUF + r * G_ST + pc, Alo + go);
        }
#pragma unroll
        for (int i = 0; i < 2; i++) {
            int idx = tid + i * 256;
            int r = idx >> 2, pc = (idx & 3) << 2;
            size_t go = (size_t)(col0 + r) * Kp + ktp + pc;
            cp16(Bh + buf * TBUF + r * G_ST + pc, Bhi + go);
            cp16(Bl + buf * TBUF + r * G_ST + pc, Blo + go);
        }
    };

    issue(0, 0); CP_COMMIT();
    int nk = Kp / 16;
    for (int t = 0; t < nk; t++) {
        int buf = t & 1;
        if (t + 1 < nk) { issue((t + 1) * 16, buf ^ 1); CP_COMMIT(); CP_WAIT(1); }
        else           { CP_WAIT(0); }
        __syncthreads();

        const uint32_t* Abh = Ah + buf * TBUF;
        const uint32_t* Abl = Al + buf * TBUF;
        const uint32_t* Bbh = Bh + buf * TBUF;
        const uint32_t* Bbl = Bl + buf * TBUF;
#pragma unroll
        for (int ks = 0; ks < 2; ks++) {
            int pb = ks * 8;
            uint32_t ah[4][4], al[4][4], bh2[2][4], bl2[2][4];
#pragma unroll
            for (int mt = 0; mt < 4; mt++) {
                int ro = (wm * 64 + mt * 16 + arow) * G_ST + apair + pb;
                ldsm4(ah[mt], Abh + ro);
                ldsm4(al[mt], Abl + ro);
            }
#pragma unroll
            for (int nt2 = 0; nt2 < 2; nt2++) {
                int ro = (wn * 32 + nt2 * 16 + brow) * G_ST + bpair + pb;
                ldsm4(bh2[nt2], Bbh + ro);
                ldsm4(bl2[nt2], Bbl + ro);
            }
#pragma unroll
            for (int mt = 0; mt < 4; mt++)
#pragma unroll
                for (int nt = 0; nt < 4; nt++) {
                    const uint32_t* bhp = &bh2[nt >> 1][(nt & 1) * 2];
                    const uint32_t* blp = &bl2[nt >> 1][(nt & 1) * 2];
                    mma3(acc[mt][nt], ah[mt], al[mt], bhp, blp);
                }
        }
        __syncthreads();
    }

#pragma unroll
    for (int mt = 0; mt < 4; mt++) {
#pragma unroll
        for (int nt = 0; nt < 4; nt++) {
            int col = col0 + wn * 32 + nt * 8 + 2 * tg;
            float2 b2 = *(const float2*)&bias[col];
            int r0 = row0 + wm * 64 + mt * 16 + g;
            if (r0 < M) {
                float2 o = { acc[mt][nt][0] * outScale + b2.x, acc[mt][nt][1] * outScale + b2.y };
                *(float2*)&C[(size_t)r0 * N + col] = o;
            }
            int r1 = r0 + 8;
            if (r1 < M) {
                float2 o = { acc[mt][nt][2] * outScale + b2.x, acc[mt][nt][3] * outScale + b2.y };
                *(float2*)&C[(size_t)r1 * N + col] = o;
            }
        }
    }
}

// ---------------------------------------------------------------------------
// Fused RMSNorm + RoPE -> packed fp16 hi/lo pairs
// ---------------------------------------------------------------------------
__global__ void rms_rope_split_kernel(const float* __restrict__ Y,
                                      const float* __restrict__ g,
                                      const float* __restrict__ freqs,
                                      const int* __restrict__ grid_sizes,
                                      uint32_t* __restrict__ ohi, uint32_t* __restrict__ olo,
                                      int L, int dim, int c)
{
    int t = blockIdx.x;
    int tid = threadIdx.x;
    const float* row = Y + (size_t)t * dim;

    float4 v = *reinterpret_cast<const float4*>(&row[4 * tid]);
    float ss = v.x * v.x + v.y * v.y + v.z * v.z + v.w * v.w;

    __shared__ float red[32];
#pragma unroll
    for (int o = 16; o > 0; o >>= 1) ss += __shfl_xor_sync(0xffffffffu, ss, o);
    int warp = tid >> 5, lane = tid & 31;
    int nwarps = blockDim.x >> 5;
    if (lane == 0) red[warp] = ss;
    __syncthreads();
    __shared__ float s_inv;
    if (tid == 0) {
        float tot = 0.f;
        for (int i = 0; i < nwarps; i++) tot += red[i];
        s_inv = rsqrtf(tot / (float)dim + 1e-6f);
    }
    __syncthreads();
    float inv = s_inv;

    float4 gg = *reinterpret_cast<const float4*>(&g[4 * tid]);
    v.x *= inv * gg.x; v.y *= inv * gg.y; v.z *= inv * gg.z; v.w *= inv * gg.w;

    int gf = grid_sizes[0], gh = grid_sizes[1], gw = grid_sizes[2];
    int hw = gh * gw;
    int sl = gf * hw;
    if (t < sl) {
        int fi = t / hw;
        int rem = t - fi * hw;
        int hi2 = rem / gw;
        int wi = rem - hi2 * gw;
        int c1 = c / 3;
        int c0 = c - 2 * c1;
#pragma unroll
        for (int pp = 0; pp < 2; pp++) {
            int p = 2 * tid + pp;
            int j = p % c;
            int idx = (j < c0) ? fi : ((j < c0 + c1) ? hi2 : wi);
            float ang = freqs[(size_t)idx * c + j];
            float sn, cs;
            sincosf(ang, &sn, &cs);
            float re = (pp == 0) ? v.x : v.z;
            float im = (pp == 0) ? v.y : v.w;
            float re2 = re * cs - im * sn;
            float im2 = re * sn + im * cs;
            if (pp == 0) { v.x = re2; v.y = im2; }
            else         { v.z = re2; v.w = im2; }
        }
    }
    size_t pbase = (size_t)t * (dim / 2) + 2 * tid;
    uint32_t h0, l0, h1, l1;
    split2(v.x, v.y, h0, l0);
    split2(v.z, v.w, h1, l1);
    ohi[pbase] = h0; olo[pbase] = l0;
    ohi[pbase + 1] = h1; olo[pbase + 1] = l1;
}

// ---------------------------------------------------------------------------
// FA2 flash attention fp16x3. CTA = 128q, 8 warps, warp tile 16q x 64k.
// Register softmax; S fragments repacked to PV A-operands in registers.
// Q/K smem [token][dpair]; V smem [d][tokenpair].
// ---------------------------------------------------------------------------
#define A_QP 68    // Q/K smem pair stride (64 data + 4 pad)
#define A_VT 36    // V smem token-pair stride (32 data + 4 pad)
__global__ void __launch_bounds__(256, 1)
attn_f16x3_kernel(const uint32_t* __restrict__ Qhi, const uint32_t* __restrict__ Qlo,
                  const uint32_t* __restrict__ Khi, const uint32_t* __restrict__ Klo,
                  const uint32_t* __restrict__ Vhi, const uint32_t* __restrict__ Vlo,
                  uint32_t* __restrict__ Ohi, uint32_t* __restrict__ Olo,
                  const int* __restrict__ seq_lens, int L, int nheads)
{
    const int QTS = 128 * A_QP;     // 8704 words per plane
    const int KTS = 64 * A_QP;      // 4352 words per plane per buf
    const int VTS = 128 * A_VT;     // 4608 words per plane per buf
    extern __shared__ uint32_t sh[];
    uint32_t* Qh = sh;                   // QTS
    uint32_t* Ql = Qh + QTS;
    uint32_t* Kh = Ql + QTS;             // 2*KTS
    uint32_t* Kl = Kh + 2 * KTS;
    uint32_t* Vh = Kl + 2 * KTS;         // 2*VTS
    uint32_t* Vl = Vh + 2 * VTS;

    int hd = blockIdx.y;
    int q0 = blockIdx.x * 128;
    int tid = threadIdx.x, lane = tid & 31, warp = tid >> 5;
    int g = lane >> 2, tg = lane & 3;
    int seqlen = seq_lens[0]; if (seqlen > L) seqlen = L;
    const float scale = rsqrtf(128.f);
    const int hq = hd * 64;     // pair offset into NPAIR row for Q/K/O
    const int hv = hd * 128;    // d-row offset into Vp

    // ldmatrix per-thread coordinates
    int marow  = (lane & 7) + ((lane & 8) ? 8 : 0);   // A-type (Q)
    int mapair = (lane & 16) ? 4 : 0;
    int nbrow  = (lane & 7) + ((lane & 16) ? 8 : 0);  // B-type (K, V)
    int nbpair = (lane & 8) ? 4 : 0;

    // Q tile (one-shot): 128 rows x 64 pairs per plane
#pragma unroll
    for (int i = 0; i < 8; i++) {
        int idx = tid + i * 256;
        int r = idx >> 4, pc = (idx & 15) << 2;
        int gr = q0 + r; if (gr >= L) gr = L - 1;
        size_t go = (size_t)gr * NPAIR + hq + pc;
        cp16(Qh + r * A_QP + pc, Qhi + go);
        cp16(Ql + r * A_QP + pc, Qlo + go);
    }
    auto issueKV = [&](int k0, int buf) {
#pragma unroll
        for (int i = 0; i < 4; i++) {
            int idx = tid + i * 256;
            int r = idx >> 4, pc = (idx & 15) << 2;
            int gr = k0 + r; if (gr >= seqlen) gr = seqlen - 1;
            size_t go = (size_t)gr * NPAIR + hq + pc;
            cp16(Kh + buf * KTS + r * A_QP + pc, Khi + go);
            cp16(Kl + buf * KTS + r * A_QP + pc, Klo + go);
        }
        int tkp0 = k0 >> 1;
#pragma unroll
        for (int i = 0; i < 4; i++) {
            int idx = tid + i * 256;
            int r = idx >> 3, pc = (idx & 7) << 2;
            size_t go = (size_t)(hv + r) * VROW + tkp0 + pc;
            cp16(Vh + buf * VTS + r * A_VT + pc, Vhi + go);
            cp16(Vl + buf * VTS + r * A_VT + pc, Vlo + go);
        }
    };
    issueKV(0, 0); CP_COMMIT();

    // per-thread softmax state: rows (warp*16 + g) and (+8)
    float rm0 = -1e30f, rm1 = -1e30f;
    float rl0 = 0.f, rl1 = 0.f;

    float acc_o[16][4];
#pragma unroll
    for (int nt = 0; nt < 16; nt++)
#pragma unroll
        for (int r = 0; r < 4; r++) acc_o[nt][r] = 0.f;

    int nkt = (seqlen + 63) >> 6;
    for (int t = 0; t < nkt; t++) {
        int buf = t & 1;
        if (t + 1 < nkt) { issueKV((t + 1) * 64, buf ^ 1); CP_COMMIT(); CP_WAIT(1); }
        else            { CP_WAIT(0); }
        __syncthreads();

        // ---- S = Q K^T : warp tile 16 x 64 ----
        const uint32_t* Kbh = Kh + buf * KTS;
        const uint32_t* Kbl = Kl + buf * KTS;
        float s[8][4];
#pragma unroll
        for (int nt = 0; nt < 8; nt++)
#pragma unroll
            for (int r = 0; r < 4; r++) s[nt][r] = 0.f;

#pragma unroll
        for (int ks = 0; ks < 8; ks++) {
            int pb = ks * 8;
            uint32_t ah[4], al[4], bh2[4][4], bl2[4][4];
            {
                int ro = (warp * 16 + marow) * A_QP + mapair + pb;
                ldsm4(ah, Qh + ro);
                ldsm4(al, Ql + ro);
            }
#pragma unroll
            for (int nt2 = 0; nt2 < 4; nt2++) {
                int ro = (nt2 * 16 + nbrow) * A_QP + nbpair + pb;
                ldsm4(bh2[nt2], Kbh + ro);
                ldsm4(bl2[nt2], Kbl + ro);
            }
#pragma unroll
            for (int nt = 0; nt < 8; nt++)
                mma3(s[nt], ah, al, &bh2[nt >> 1][(nt & 1) * 2], &bl2[nt >> 1][(nt & 1) * 2]);
        }

        // ---- register softmax ----
        int k0 = t * 64;
        if (k0 + 64 <= seqlen) {
#pragma unroll
            for (int nt = 0; nt < 8; nt++)
#pragma unroll
                for (int r = 0; r < 4; r++) s[nt][r] *= scale;
        } else {
#pragma unroll
            for (int nt = 0; nt < 8; nt++) {
                int colb = k0 + nt * 8 + 2 * tg;
#pragma unroll
                for (int r = 0; r < 4; r++) {
                    int col = colb + (r & 1);
                    s[nt][r] = (col < seqlen) ? s[nt][r] * scale : -1e30f;
                }
            }
        }
        float mx0 = rm0, mx1 = rm1;
#pragma unroll
        for (int nt = 0; nt < 8; nt++) {
            mx0 = fmaxf(mx0, fmaxf(s[nt][0], s[nt][1]));
            mx1 = fmaxf(mx1, fmaxf(s[nt][2], s[nt][3]));
        }
        mx0 = fmaxf(mx0, __shfl_xor_sync(0xffffffffu, mx0, 1));
        mx0 = fmaxf(mx0, __shfl_xor_sync(0xffffffffu, mx0, 2));
        mx1 = fmaxf(mx1, __shfl_xor_sync(0xffffffffu, mx1, 1));
        mx1 = fmaxf(mx1, __shfl_xor_sync(0xffffffffu, mx1, 2));
        float cf0 = __expf(rm0 - mx0);
        float cf1 = __expf(rm1 - mx1);
        rm0 = mx0; rm1 = mx1;
        float ls0 = 0.f, ls1 = 0.f;
#pragma unroll
        for (int nt = 0; nt < 8; nt++) {
            s[nt][0] = __expf(s[nt][0] - mx0); ls0 += s[nt][0];
            s[nt][1] = __expf(s[nt][1] - mx0); ls0 += s[nt][1];
            s[nt][2] = __expf(s[nt][2] - mx1); ls1 += s[nt][2];
            s[nt][3] = __expf(s[nt][3] - mx1); ls1 += s[nt][3];
        }
        ls0 += __shfl_xor_sync(0xffffffffu, ls0, 1);
        ls0 += __shfl_xor_sync(0xffffffffu, ls0, 2);
        ls1 += __shfl_xor_sync(0xffffffffu, ls1, 1);
        ls1 += __shfl_xor_sync(0xffffffffu, ls1, 2);
        rl0 = rl0 * cf0 + ls0;
        rl1 = rl1 * cf1 + ls1;

        // ---- repack S fragments -> PV A-operand fragments (hi/lo) ----
        // PV k-step kc covers keys [16kc,16kc+16): A frag regs come from
        // S tiles nt=2kc (keys 8kc..) and nt=2kc+1.
        uint32_t pa_h[4][4], pa_l[4][4];
#pragma unroll
        for (int kc = 0; kc < 4; kc++) {
            split2(s[2 * kc][0],     s[2 * kc][1],     pa_h[kc][0], pa_l[kc][0]);
            split2(s[2 * kc][2],     s[2 * kc][3],     pa_h[kc][1], pa_l[kc][1]);
            split2(s[2 * kc + 1][0], s[2 * kc + 1][1], pa_h[kc][2], pa_l[kc][2]);
            split2(s[2 * kc + 1][2], s[2 * kc + 1][3], pa_h[kc][3], pa_l[kc][3]);
        }

        // ---- rescale O ----
#pragma unroll
        for (int nt = 0; nt < 16; nt++) {
            acc_o[nt][0] *= cf0; acc_o[nt][1] *= cf0;
            acc_o[nt][2] *= cf1; acc_o[nt][3] *= cf1;
        }

        // ---- O += P @ V : warp tile 16 x 128 ----
        const uint32_t* Vbh = Vh + buf * VTS;
        const uint32_t* Vbl = Vl + buf * VTS;
#pragma unroll
        for (int nh = 0; nh < 2; nh++) {
#pragma unroll
            for (int ks = 0; ks < 4; ks++) {
                int pb = ks * 8;
                uint32_t bh2[4][4], bl2[4][4];
#pragma unroll
                for (int nt2 = 0; nt2 < 4; nt2++) {
                    int ro = ((nh * 4 + nt2) * 16 + nbrow) * A_VT + nbpair + pb;
                    ldsm4(bh2[nt2], Vbh + ro);
                    ldsm4(bl2[nt2], Vbl + ro);
                }
#pragma unroll
                for (int nt = 0; nt < 8; nt++)
                    mma3(acc_o[nh * 8 + nt], pa_h[ks], pa_l[ks],
                         &bh2[nt >> 1][(nt & 1) * 2], &bl2[nt >> 1][(nt & 1) * 2]);
            }
        }
        __syncthreads();
    }

    // ---- epilogue: normalize + store packed pairs ----
    float il0 = 1.f / rl0;
    float il1 = 1.f / rl1;
    int r0 = warp * 16 + g;
#pragma unroll
    for (int nt = 0; nt < 16; nt++) {
        int pidx = nt * 4 + tg;      // pair index within head (64 pairs)
        int gr0 = q0 + r0;
        if (gr0 < L) {
            uint32_t hh, ll;
            split2(acc_o[nt][0] * il0, acc_o[nt][1] * il0, hh, ll);
            Ohi[(size_t)gr0 * NPAIR + hq + pidx] = hh;
            Olo[(size_t)gr0 * NPAIR + hq + pidx] = ll;
        }
        int gr1 = gr0 + 8;
        if (gr1 < L) {
            uint32_t hh, ll;
            split2(acc_o[nt][2] * il1, acc_o[nt][3] * il1, hh, ll);
            Ohi[(size_t)gr1 * NPAIR + hq + pidx] = hh;
            Olo[(size_t)gr1 * NPAIR + hq + pidx] = ll;
        }
    }
}

// ---------------------------------------------------------------------------
// Host launcher
// ---------------------------------------------------------------------------
extern "C" void kernel_launch(void* const* d_in, const int* in_sizes, int n_in,
                              void* d_out, int out_size)
{
    const float* x        = (const float*)d_in[0];
    const int*   seq_lens = (const int*)  d_in[1];
    const int*   grid_szs = (const int*)  d_in[2];
    const float* freqs    = (const float*)d_in[3];
    const float* Wq       = (const float*)d_in[4];
    const float* bq       = (const float*)d_in[5];
    const float* Wk       = (const float*)d_in[6];
    const float* bk       = (const float*)d_in[7];
    const float* Wv       = (const float*)d_in[8];
    const float* bv       = (const float*)d_in[9];
    const float* Wo       = (const float*)d_in[10];
    const float* bo       = (const float*)d_in[11];
    const float* gq       = (const float*)d_in[12];
    const float* gk       = (const float*)d_in[13];

    int dim = in_sizes[5];            // 1536
    int L   = in_sizes[0] / dim;      // 5000
    int c   = in_sizes[3] / 1024;     // 64
    int dh  = 2 * c;                  // 128
    int n   = dim / dh;               // 12
    int Kp  = dim / 2;                // 768

    float *Qb, *Kb, *Vb;
    uint32_t *xp, *wp, *qp, *kp, *vp, *op;
    cudaGetSymbolAddress((void**)&Qb, g_Q);
    cudaGetSymbolAddress((void**)&Kb, g_K);
    cudaGetSymbolAddress((void**)&Vb, g_V);
    cudaGetSymbolAddress((void**)&xp, g_Xp);
    cudaGetSymbolAddress((void**)&wp, g_Wp);
    cudaGetSymbolAddress((void**)&qp, g_Qp);
    cudaGetSymbolAddress((void**)&kp, g_Kp);
    cudaGetSymbolAddress((void**)&vp, g_Vp);
    cudaGetSymbolAddress((void**)&op, g_Op);

    const size_t PLANE = (size_t)MAX_L * NPAIR;
    const size_t WSZ   = (size_t)NPAIR * DIMV;
    const size_t VPLN  = (size_t)DIMV * VROW;
    uint32_t* xp_h = xp;            uint32_t* xp_l = xp + PLANE;
    uint32_t* qp_h = qp;            uint32_t* qp_l = qp + PLANE;
    uint32_t* kp_h = kp;            uint32_t* kp_l = kp + PLANE;
    uint32_t* op_h = op;            uint32_t* op_l = op + PLANE;
    uint32_t* vp_h = vp;            uint32_t* vp_l = vp + VPLN;
    const float WS = 256.f, IWS = 1.f / 256.f;

    size_t gsmem = (size_t)(4 * 2 * 128 * G_ST) * 4;                              // 81920
    size_t asmem = (size_t)(2 * 128 * A_QP + 4 * 64 * A_QP + 4 * 128 * A_VT) * 4; // 212992
    cudaFuncSetAttribute(gemm_f16x3_kernel, cudaFuncAttributeMaxDynamicSharedMemorySize, (int)gsmem);
    cudaFuncSetAttribute(attn_f16x3_kernel, cudaFuncAttributeMaxDynamicSharedMemorySize, (int)asmem);

    // ---- prep: splits ----
    int npx = L * Kp;
    split_rows_kernel<<<(npx + 255) / 256, 256>>>(x, xp_h, xp_l, npx);
    {
        dim3 tg(32, 8), tgr(dim / 32, (dim + 63) / 64);
        split_trans_kernel<<<tgr, tg>>>(Wq, wp + 0 * WSZ, wp + 1 * WSZ, dim, dim, Kp, WS);
        split_trans_kernel<<<tgr, tg>>>(Wk, wp + 2 * WSZ, wp + 3 * WSZ, dim, dim, Kp, WS);
        split_trans_kernel<<<tgr, tg>>>(Wv, wp + 4 * WSZ, wp + 5 * WSZ, dim, dim, Kp, WS);
        split_trans_kernel<<<tgr, tg>>>(Wo, wp + 6 * WSZ, wp + 7 * WSZ, dim, dim, Kp, WS);
    }

    // ---- projections ----
    dim3 ggrid((L + 127) / 128, dim / 128);
    gemm_f16x3_kernel<<<ggrid, 256, gsmem>>>(xp_h, xp_l, wp + 0 * WSZ, wp + 1 * WSZ, bq, Qb, L, dim, Kp, IWS);
    gemm_f16x3_kernel<<<ggrid, 256, gsmem>>>(xp_h, xp_l, wp + 2 * WSZ, wp + 3 * WSZ, bk, Kb, L, dim, Kp, IWS);
    gemm_f16x3_kernel<<<ggrid, 256, gsmem>>>(xp_h, xp_l, wp + 4 * WSZ, wp + 5 * WSZ, bv, Vb, L, dim, Kp, IWS);

    // ---- norm + rope -> packed Q/K; transpose-split V ----
    rms_rope_split_kernel<<<L, dim / 4>>>(Qb, gq, freqs, grid_szs, qp_h, qp_l, L, dim, c);
    rms_rope_split_kernel<<<L, dim / 4>>>(Kb, gk, freqs, grid_szs, kp_h, kp_l, L, dim, c);
    {
        dim3 tg(32, 8), tgr(dim / 32, (L + 63) / 64);
        split_trans_kernel<<<tgr, tg>>>(Vb, vp_h, vp_l, L, dim, VROW, 1.f);
    }

    // ---- attention ----
    attn_f16x3_kernel<<<dim3((L + 127) / 128, n), 256, asmem>>>(
        qp_h, qp_l, kp_h, kp_l, vp_h, vp_l, op_h, op_l, seq_lens, L, n);

    // ---- output projection ----
    gemm_f16x3_kernel<<<ggrid, 256, gsmem>>>(op_h, op_l, wp + 6 * WSZ, wp + 7 * WSZ, bo, (float*)d_out, L, dim, Kp, IWS);
}

// round 13
// speedup vs baseline: 1.4158x; 1.4158x over previous
#include <cuda_runtime.h>
#include <cuda_fp16.h>
#include <math.h>
#include <stdint.h>

// ---------------------------------------------------------------------------
// WanSelfAttention: B=1, L=5000, dim=1536, heads=12, head_dim=128, fp32 I/O.
// R12: revert to R7 structure (best: 2820us). fp16x3 error-compensated tensor
// cores + ldmatrix. NEW: P (softmax output) kept in plain fp16 -> PV uses 2
// mmas instead of 3 and the Pl smem plane disappears. S / GEMMs stay x3.
// ---------------------------------------------------------------------------

#define MAX_L 5120
#define DIMV  1536
#define NPAIR 768            // DIMV/2
#define VROW  (MAX_L / 2)    // token-pairs per d row

// fp32 intermediates
__device__ float g_Q[MAX_L * DIMV];
__device__ float g_K[MAX_L * DIMV];
__device__ float g_V[MAX_L * DIMV];
// packed fp16 hi/lo pair buffers
__device__ uint32_t g_Xp[2][MAX_L * NPAIR];        // x: [token][kpair]
__device__ uint32_t g_Wp[8][NPAIR * DIMV];         // W transposed: [n][kpair]
__device__ uint32_t g_Qp[2][MAX_L * NPAIR];        // [token][dpair]
__device__ uint32_t g_Kp[2][MAX_L * NPAIR];
__device__ uint32_t g_Vp[2][DIMV * VROW];          // V transposed: [d][tokenpair]
__device__ uint32_t g_Op[2][MAX_L * NPAIR];

// ---------------- helpers ----------------
__device__ __forceinline__ void cp16(void* smem_dst, const void* gsrc) {
    uint32_t s = (uint32_t)__cvta_generic_to_shared(smem_dst);
    asm volatile("cp.async.cg.shared.global [%0], [%1], 16;\n" :: "r"(s), "l"(gsrc));
}
#define CP_COMMIT() asm volatile("cp.async.commit_group;\n" ::: "memory")
#define CP_WAIT(n)  asm volatile("cp.async.wait_group %0;\n" :: "n"(n) : "memory")

__device__ __forceinline__ void ldsm4(uint32_t* r, const uint32_t* p) {
    uint32_t a = (uint32_t)__cvta_generic_to_shared(p);
    asm volatile("ldmatrix.sync.aligned.m8n8.x4.shared.b16 {%0,%1,%2,%3}, [%4];"
        : "=r"(r[0]), "=r"(r[1]), "=r"(r[2]), "=r"(r[3]) : "r"(a));
}

__device__ __forceinline__ void split2(float x, float y, uint32_t& hi, uint32_t& lo) {
    __half2 h = __floats2half2_rn(x, y);
    float2 hf = __half22float2(h);
    __half2 l = __floats2half2_rn(x - hf.x, y - hf.y);
    hi = *reinterpret_cast<uint32_t*>(&h);
    lo = *reinterpret_cast<uint32_t*>(&l);
}

__device__ __forceinline__ void mma_f16(float* c, const uint32_t* a, const uint32_t* b) {
    asm volatile(
        "mma.sync.aligned.m16n8k16.row.col.f32.f16.f16.f32 "
        "{%0,%1,%2,%3}, {%4,%5,%6,%7}, {%8,%9}, {%0,%1,%2,%3};\n"
        : "+f"(c[0]), "+f"(c[1]), "+f"(c[2]), "+f"(c[3])
        : "r"(a[0]), "r"(a[1]), "r"(a[2]), "r"(a[3]), "r"(b[0]), "r"(b[1]));
}
__device__ __forceinline__ void mma3(float* c,
                                     const uint32_t* ah, const uint32_t* al,
                                     const uint32_t* bh, const uint32_t* bl) {
    mma_f16(c, al, bh);
    mma_f16(c, ah, bl);
    mma_f16(c, ah, bh);
}
// 2-term variant: A is exact in fp16 (P), B split hi/lo
__device__ __forceinline__ void mma2(float* c, const uint32_t* a,
                                     const uint32_t* bh, const uint32_t* bl) {
    mma_f16(c, a, bl);
    mma_f16(c, a, bh);
}

// ---------------------------------------------------------------------------
// Prep kernels
// ---------------------------------------------------------------------------
__global__ void split_rows_kernel(const float* __restrict__ X,
                                  uint32_t* __restrict__ hi, uint32_t* __restrict__ lo,
                                  int npairs)
{
    int i = blockIdx.x * 256 + threadIdx.x;
    if (i >= npairs) return;
    float2 v = reinterpret_cast<const float2*>(X)[i];
    uint32_t h, l; split2(v.x, v.y, h, l);
    hi[i] = h; lo[i] = l;
}

__global__ void split_trans_kernel(const float* __restrict__ X,
                                   uint32_t* __restrict__ hi, uint32_t* __restrict__ lo,
                                   int R, int C, int RPstride, float scale)
{
    __shared__ float tile[64][33];
    int r0 = blockIdx.y * 64, c0 = blockIdx.x * 32;
    int tx = threadIdx.x, ty = threadIdx.y;   // 32 x 8
#pragma unroll
    for (int i = 0; i < 8; i++) {
        int r = r0 + ty + i * 8;
        float v = 0.f;
        if (r < R && c0 + tx < C) v = X[(size_t)r * C + c0 + tx] * scale;
        tile[ty + i * 8][tx] = v;
    }
    __syncthreads();
#pragma unroll
    for (int i = 0; i < 4; i++) {
        int cy = ty + i * 8;
        int cc = c0 + cy;
        int rp = (r0 >> 1) + tx;
        if (cc < C && 2 * rp < R) {
            uint32_t h, l;
            split2(tile[2 * tx][cy], tile[2 * tx + 1][cy], h, l);
            hi[(size_t)cc * RPstride + rp] = h;
            lo[(size_t)cc * RPstride + rp] = l;
        }
    }
}

// ---------------------------------------------------------------------------
// GEMM fp16x3 (R7 design): C[M,N] = (Ap @ Bp^T) * outScale + bias
// ---------------------------------------------------------------------------
#define G_ST 20
__global__ void __launch_bounds__(256)
gemm_f16x3_kernel(const uint32_t* __restrict__ Ahi, const uint32_t* __restrict__ Alo,
                  const uint32_t* __restrict__ Bhi, const uint32_t* __restrict__ Blo,
                  const float* __restrict__ bias, float* __restrict__ C,
                  int M, int N, int Kp, float outScale)
{
    const int TBUF = 128 * G_ST;
    extern __shared__ uint32_t sh[];
    uint32_t* Ah = sh;
    uint32_t* Al = Ah + 2 * TBUF;
    uint32_t* Bh = Al + 2 * TBUF;
    uint32_t* Bl = Bh + 2 * TBUF;

    int tid = threadIdx.x;
    int lane = tid & 31, warp = tid >> 5;
    int wm = warp >> 2, wn = warp & 3;
    int g = lane >> 2, tg = lane & 3;
    int row0 = blockIdx.x * 128, col0 = blockIdx.y * 128;

    int arow  = (lane & 7) + ((lane & 8) ? 8 : 0);
    int apair = (lane & 16) ? 4 : 0;
    int brow  = (lane & 7) + ((lane & 16) ? 8 : 0);
    int bpair = (lane & 8) ? 4 : 0;

    float acc[4][4][4];
#pragma unroll
    for (int mt = 0; mt < 4; mt++)
#pragma unroll
        for (int nt = 0; nt < 4; nt++)
#pragma unroll
            for (int r = 0; r < 4; r++) acc[mt][nt][r] = 0.f;

    auto issue = [&](int ktp, int buf) {
#pragma unroll
        for (int i = 0; i < 2; i++) {
            int idx = tid + i * 256;
            int r = idx >> 2, pc = (idx & 3) << 2;
            int gr = row0 + r; if (gr >= M) gr = M - 1;
            size_t go = (size_t)gr * Kp + ktp + pc;
            cp16(Ah + buf * TBUF + r * G_ST + pc, Ahi + go);
            cp16(Al + buf * TBUF + r * G_ST + pc, Alo + go);
        }
#pragma unroll
        for (int i = 0; i < 2; i++) {
            int idx = tid + i * 256;
            int r = idx >> 2, pc = (idx & 3) << 2;
            size_t go = (size_t)(col0 + r) * Kp + ktp + pc;
            cp16(Bh + buf * TBUF + r * G_ST + pc, Bhi + go);
            cp16(Bl + buf * TBUF + r * G_ST + pc, Blo + go);
        }
    };

    issue(0, 0); CP_COMMIT();
    int nk = Kp / 16;
    for (int t = 0; t < nk; t++) {
        int buf = t & 1;
        if (t + 1 < nk) { issue((t + 1) * 16, buf ^ 1); CP_COMMIT(); CP_WAIT(1); }
        else           { CP_WAIT(0); }
        __syncthreads();

        const uint32_t* Abh = Ah + buf * TBUF;
        const uint32_t* Abl = Al + buf * TBUF;
        const uint32_t* Bbh = Bh + buf * TBUF;
        const uint32_t* Bbl = Bl + buf * TBUF;
#pragma unroll
        for (int ks = 0; ks < 2; ks++) {
            int pb = ks * 8;
            uint32_t ah[4][4], al[4][4], bh2[2][4], bl2[2][4];
#pragma unroll
            for (int mt = 0; mt < 4; mt++) {
                int ro = (wm * 64 + mt * 16 + arow) * G_ST + apair + pb;
                ldsm4(ah[mt], Abh + ro);
                ldsm4(al[mt], Abl + ro);
            }
#pragma unroll
            for (int nt2 = 0; nt2 < 2; nt2++) {
                int ro = (wn * 32 + nt2 * 16 + brow) * G_ST + bpair + pb;
                ldsm4(bh2[nt2], Bbh + ro);
                ldsm4(bl2[nt2], Bbl + ro);
            }
#pragma unroll
            for (int mt = 0; mt < 4; mt++)
#pragma unroll
                for (int nt = 0; nt < 4; nt++) {
                    const uint32_t* bhp = &bh2[nt >> 1][(nt & 1) * 2];
                    const uint32_t* blp = &bl2[nt >> 1][(nt & 1) * 2];
                    mma3(acc[mt][nt], ah[mt], al[mt], bhp, blp);
                }
        }
        __syncthreads();
    }

#pragma unroll
    for (int mt = 0; mt < 4; mt++) {
#pragma unroll
        for (int nt = 0; nt < 4; nt++) {
            int col = col0 + wn * 32 + nt * 8 + 2 * tg;
            float2 b2 = *(const float2*)&bias[col];
            int r0 = row0 + wm * 64 + mt * 16 + g;
            if (r0 < M) {
                float2 o = { acc[mt][nt][0] * outScale + b2.x, acc[mt][nt][1] * outScale + b2.y };
                *(float2*)&C[(size_t)r0 * N + col] = o;
            }
            int r1 = r0 + 8;
            if (r1 < M) {
                float2 o = { acc[mt][nt][2] * outScale + b2.x, acc[mt][nt][3] * outScale + b2.y };
                *(float2*)&C[(size_t)r1 * N + col] = o;
            }
        }
    }
}

// ---------------------------------------------------------------------------
// Fused RMSNorm + RoPE -> packed fp16 hi/lo pairs
// ---------------------------------------------------------------------------
__global__ void rms_rope_split_kernel(const float* __restrict__ Y,
                                      const float* __restrict__ g,
                                      const float* __restrict__ freqs,
                                      const int* __restrict__ grid_sizes,
                                      uint32_t* __restrict__ ohi, uint32_t* __restrict__ olo,
                                      int L, int dim, int c)
{
    int t = blockIdx.x;
    int tid = threadIdx.x;
    const float* row = Y + (size_t)t * dim;

    float4 v = *reinterpret_cast<const float4*>(&row[4 * tid]);
    float ss = v.x * v.x + v.y * v.y + v.z * v.z + v.w * v.w;

    __shared__ float red[32];
#pragma unroll
    for (int o = 16; o > 0; o >>= 1) ss += __shfl_xor_sync(0xffffffffu, ss, o);
    int warp = tid >> 5, lane = tid & 31;
    int nwarps = blockDim.x >> 5;
    if (lane == 0) red[warp] = ss;
    __syncthreads();
    __shared__ float s_inv;
    if (tid == 0) {
        float tot = 0.f;
        for (int i = 0; i < nwarps; i++) tot += red[i];
        s_inv = rsqrtf(tot / (float)dim + 1e-6f);
    }
    __syncthreads();
    float inv = s_inv;

    float4 gg = *reinterpret_cast<const float4*>(&g[4 * tid]);
    v.x *= inv * gg.x; v.y *= inv * gg.y; v.z *= inv * gg.z; v.w *= inv * gg.w;

    int gf = grid_sizes[0], gh = grid_sizes[1], gw = grid_sizes[2];
    int hw = gh * gw;
    int sl = gf * hw;
    if (t < sl) {
        int fi = t / hw;
        int rem = t - fi * hw;
        int hi2 = rem / gw;
        int wi = rem - hi2 * gw;
        int c1 = c / 3;
        int c0 = c - 2 * c1;
#pragma unroll
        for (int pp = 0; pp < 2; pp++) {
            int p = 2 * tid + pp;
            int j = p % c;
            int idx = (j < c0) ? fi : ((j < c0 + c1) ? hi2 : wi);
            float ang = freqs[(size_t)idx * c + j];
            float sn, cs;
            sincosf(ang, &sn, &cs);
            float re = (pp == 0) ? v.x : v.z;
            float im = (pp == 0) ? v.y : v.w;
            float re2 = re * cs - im * sn;
            float im2 = re * sn + im * cs;
            if (pp == 0) { v.x = re2; v.y = im2; }
            else         { v.z = re2; v.w = im2; }
        }
    }
    size_t pbase = (size_t)t * (dim / 2) + 2 * tid;
    uint32_t h0, l0, h1, l1;
    split2(v.x, v.y, h0, l0);
    split2(v.z, v.w, h1, l1);
    ohi[pbase] = h0; olo[pbase] = l0;
    ohi[pbase + 1] = h1; olo[pbase + 1] = l1;
}

// ---------------------------------------------------------------------------
// Flash attention (R7 layout). 64q x 64k tiles, d=128 (64 pairs).
// 256 thr, warps 2x4. S warp tile 32x16 (2x2, fp16x3). PV warp tile 32x32
// (2x4, fp16 P x split V -> 2 mmas). K/V double-buffered cp.async.
// ---------------------------------------------------------------------------
#define A_QP 68    // Q/K smem pair stride (64 data + pad)
#define A_VT 36    // V smem token-pair stride (32 data + pad)
#define A_PP 36    // P smem pair stride (32 data + pad)
#define A_SS 68    // fp32 S stride
__global__ void __launch_bounds__(256, 1)
attn_f16x3_kernel(const uint32_t* __restrict__ Qhi, const uint32_t* __restrict__ Qlo,
                  const uint32_t* __restrict__ Khi, const uint32_t* __restrict__ Klo,
                  const uint32_t* __restrict__ Vhi, const uint32_t* __restrict__ Vlo,
                  uint32_t* __restrict__ Ohi, uint32_t* __restrict__ Olo,
                  const int* __restrict__ seq_lens, int L, int nheads)
{
    const int QTS = 64 * A_QP;      // 4352
    const int VTS = 128 * A_VT;     // 4608
    extern __shared__ uint32_t sh[];
    uint32_t* Qh = sh;                   // QTS
    uint32_t* Ql = Qh + QTS;
    uint32_t* Kh = Ql + QTS;             // 2*QTS
    uint32_t* Kl = Kh + 2 * QTS;
    uint32_t* Vh = Kl + 2 * QTS;         // 2*VTS
    uint32_t* Vl = Vh + 2 * VTS;
    uint32_t* Ph = Vl + 2 * VTS;         // 64*A_PP  (fp16 P, hi only)
    float*    Ps = (float*)(Ph + 64 * A_PP);   // 64*A_SS
    float*    s_m = Ps + 64 * A_SS;
    float*    s_l = s_m + 64;
    float*    s_c = s_l + 64;

    int hd = blockIdx.y;
    int q0 = blockIdx.x * 64;
    int tid = threadIdx.x, lane = tid & 31, warp = tid >> 5;
    int wm = warp >> 2, wn = warp & 3;
    int g = lane >> 2, tg = lane & 3;
    int seqlen = seq_lens[0]; if (seqlen > L) seqlen = L;
    const float scale = rsqrtf(128.f);
    const int hq = hd * 64;     // pair offset into NPAIR row for Q/K/O
    const int hv = hd * 128;    // d-row offset into Vp

    // ldmatrix per-thread coordinates
    int marow  = (lane & 7) + ((lane & 8) ? 8 : 0);   // A-type (Q, P)
    int mapair = (lane & 16) ? 4 : 0;
    int nbrow  = (lane & 7) + ((lane & 16) ? 8 : 0);  // B-type (K, V)
    int nbpair = (lane & 8) ? 4 : 0;

    // Q tile (one-shot)
#pragma unroll
    for (int i = 0; i < 4; i++) {
        int idx = tid + i * 256;
        int r = idx >> 4, pc = (idx & 15) << 2;
        int gr = q0 + r; if (gr >= L) gr = L - 1;
        size_t go = (size_t)gr * NPAIR + hq + pc;
        cp16(Qh + r * A_QP + pc, Qhi + go);
        cp16(Ql + r * A_QP + pc, Qlo + go);
    }
    auto issueKV = [&](int k0, int buf) {
#pragma unroll
        for (int i = 0; i < 4; i++) {
            int idx = tid + i * 256;
            int r = idx >> 4, pc = (idx & 15) << 2;
            int gr = k0 + r; if (gr >= seqlen) gr = seqlen - 1;
            size_t go = (size_t)gr * NPAIR + hq + pc;
            cp16(Kh + buf * QTS + r * A_QP + pc, Khi + go);
            cp16(Kl + buf * QTS + r * A_QP + pc, Klo + go);
        }
        int tkp0 = k0 >> 1;
#pragma unroll
        for (int i = 0; i < 4; i++) {
            int idx = tid + i * 256;
            int r = idx >> 3, pc = (idx & 7) << 2;    // r: d row 0..127
            size_t go = (size_t)(hv + r) * VROW + tkp0 + pc;
            cp16(Vh + buf * VTS + r * A_VT + pc, Vhi + go);
            cp16(Vl + buf * VTS + r * A_VT + pc, Vlo + go);
        }
    };
    issueKV(0, 0); CP_COMMIT();

    if (tid < 64) { s_m[tid] = -1e30f; s_l[tid] = 0.f; }

    float acc_o[2][4][4];
#pragma unroll
    for (int mt = 0; mt < 2; mt++)
#pragma unroll
        for (int nt = 0; nt < 4; nt++)
#pragma unroll
            for (int r = 0; r < 4; r++) acc_o[mt][nt][r] = 0.f;

    int nkt = (seqlen + 63) >> 6;
    for (int t = 0; t < nkt; t++) {
        int buf = t & 1;
        if (t + 1 < nkt) { issueKV((t + 1) * 64, buf ^ 1); CP_COMMIT(); CP_WAIT(1); }
        else            { CP_WAIT(0); }
        __syncthreads();

        // ---- S = Q K^T (fp16x3) ----
        const uint32_t* Kbh = Kh + buf * QTS;
        const uint32_t* Kbl = Kl + buf * QTS;
        float acc_s[2][2][4];
#pragma unroll
        for (int mt = 0; mt < 2; mt++)
#pragma unroll
            for (int nt = 0; nt < 2; nt++)
#pragma unroll
                for (int r = 0; r < 4; r++) acc_s[mt][nt][r] = 0.f;

#pragma unroll
        for (int ks = 0; ks < 8; ks++) {
            int pb = ks * 8;
            uint32_t ah[2][4], al[2][4], bh2[4], bl2[4];
#pragma unroll
            for (int mt = 0; mt < 2; mt++) {
                int ro = (wm * 32 + mt * 16 + marow) * A_QP + mapair + pb;
                ldsm4(ah[mt], Qh + ro);
                ldsm4(al[mt], Ql + ro);
            }
            {
                int ro = (wn * 16 + nbrow) * A_QP + nbpair + pb;
                ldsm4(bh2, Kbh + ro);
                ldsm4(bl2, Kbl + ro);
            }
#pragma unroll
            for (int mt = 0; mt < 2; mt++)
#pragma unroll
                for (int nt = 0; nt < 2; nt++)
                    mma3(acc_s[mt][nt], ah[mt], al[mt], &bh2[nt * 2], &bl2[nt * 2]);
        }
        // write fp32 S
#pragma unroll
        for (int mt = 0; mt < 2; mt++) {
            int r0 = wm * 32 + mt * 16 + g;
#pragma unroll
            for (int nt = 0; nt < 2; nt++) {
                int cc = wn * 16 + nt * 8 + 2 * tg;
                *(float2*)&Ps[r0 * A_SS + cc]       = make_float2(acc_s[mt][nt][0], acc_s[mt][nt][1]);
                *(float2*)&Ps[(r0 + 8) * A_SS + cc] = make_float2(acc_s[mt][nt][2], acc_s[mt][nt][3]);
            }
        }
        __syncthreads();

        // ---- online softmax: 4 threads per row; emit fp16 P (hi only) ----
        {
            int row = tid >> 2, sub = tid & 3;
            int k0 = t * 64;
            const float* pr = Ps + row * A_SS + sub * 16;
            float vals[16];
            float mx = -1e30f;
#pragma unroll
            for (int j = 0; j < 16; j++) {
                int col = sub * 16 + j;
                float vv = (k0 + col < seqlen) ? pr[j] * scale : -1e30f;
                vals[j] = vv;
                mx = fmaxf(mx, vv);
            }
            mx = fmaxf(mx, __shfl_xor_sync(0xffffffffu, mx, 1));
            mx = fmaxf(mx, __shfl_xor_sync(0xffffffffu, mx, 2));
            float mold = s_m[row];
            float mnew = fmaxf(mold, mx);
            float ls = 0.f;
#pragma unroll
            for (int j = 0; j < 16; j++) {
                vals[j] = __expf(vals[j] - mnew);
                ls += vals[j];
            }
#pragma unroll
            for (int jp = 0; jp < 8; jp++) {
                __half2 hh = __floats2half2_rn(vals[2 * jp], vals[2 * jp + 1]);
                Ph[row * A_PP + sub * 8 + jp] = *reinterpret_cast<uint32_t*>(&hh);
            }
            ls += __shfl_xor_sync(0xffffffffu, ls, 1);
            ls += __shfl_xor_sync(0xffffffffu, ls, 2);
            if (sub == 0) {
                float cf = __expf(mold - mnew);
                s_m[row] = mnew;
                s_l[row] = s_l[row] * cf + ls;
                s_c[row] = cf;
            }
        }
        __syncthreads();

        // ---- rescale + O += P @ V (P fp16, V split: 2 mmas) ----
        const uint32_t* Vbh = Vh + buf * VTS;
        const uint32_t* Vbl = Vl + buf * VTS;
#pragma unroll
        for (int mt = 0; mt < 2; mt++) {
            int r0 = wm * 32 + mt * 16 + g;
            float cf0 = s_c[r0], cf1 = s_c[r0 + 8];
#pragma unroll
            for (int nt = 0; nt < 4; nt++) {
                acc_o[mt][nt][0] *= cf0; acc_o[mt][nt][1] *= cf0;
                acc_o[mt][nt][2] *= cf1; acc_o[mt][nt][3] *= cf1;
            }
        }
#pragma unroll
        for (int ks = 0; ks < 4; ks++) {
            int pb = ks * 8;
            uint32_t ah[2][4], bh2[2][4], bl2[2][4];
#pragma unroll
            for (int mt = 0; mt < 2; mt++) {
                int ro = (wm * 32 + mt * 16 + marow) * A_PP + mapair + pb;
                ldsm4(ah[mt], Ph + ro);
            }
#pragma unroll
            for (int nt2 = 0; nt2 < 2; nt2++) {
                int ro = (wn * 32 + nt2 * 16 + nbrow) * A_VT + nbpair + pb;
                ldsm4(bh2[nt2], Vbh + ro);
                ldsm4(bl2[nt2], Vbl + ro);
            }
#pragma unroll
            for (int mt = 0; mt < 2; mt++)
#pragma unroll
                for (int nt = 0; nt < 4; nt++) {
                    const uint32_t* bhp = &bh2[nt >> 1][(nt & 1) * 2];
                    const uint32_t* blp = &bl2[nt >> 1][(nt & 1) * 2];
                    mma2(acc_o[mt][nt], ah[mt], bhp, blp);
                }
        }
        __syncthreads();
    }

    // ---- epilogue: normalize + store packed pairs ----
#pragma unroll
    for (int mt = 0; mt < 2; mt++) {
        int r0 = wm * 32 + mt * 16 + g;
        float il0 = 1.f / s_l[r0];
        float il1 = 1.f / s_l[r0 + 8];
#pragma unroll
        for (int nt = 0; nt < 4; nt++) {
            int pidx = wn * 16 + nt * 4 + tg;      // pair index within head
            int gr0 = q0 + r0;
            if (gr0 < L) {
                uint32_t hh, ll;
                split2(acc_o[mt][nt][0] * il0, acc_o[mt][nt][1] * il0, hh, ll);
                Ohi[(size_t)gr0 * NPAIR + hq + pidx] = hh;
                Olo[(size_t)gr0 * NPAIR + hq + pidx] = ll;
            }
            int gr1 = gr0 + 8;
            if (gr1 < L) {
                uint32_t hh, ll;
                split2(acc_o[mt][nt][2] * il1, acc_o[mt][nt][3] * il1, hh, ll);
                Ohi[(size_t)gr1 * NPAIR + hq + pidx] = hh;
                Olo[(size_t)gr1 * NPAIR + hq + pidx] = ll;
            }
        }
    }
}

// ---------------------------------------------------------------------------
// Host launcher
// ---------------------------------------------------------------------------
extern "C" void kernel_launch(void* const* d_in, const int* in_sizes, int n_in,
                              void* d_out, int out_size)
{
    const float* x        = (const float*)d_in[0];
    const int*   seq_lens = (const int*)  d_in[1];
    const int*   grid_szs = (const int*)  d_in[2];
    const float* freqs    = (const float*)d_in[3];
    const float* Wq       = (const float*)d_in[4];
    const float* bq       = (const float*)d_in[5];
    const float* Wk       = (const float*)d_in[6];
    const float* bk       = (const float*)d_in[7];
    const float* Wv       = (const float*)d_in[8];
    const float* bv       = (const float*)d_in[9];
    const float* Wo       = (const float*)d_in[10];
    const float* bo       = (const float*)d_in[11];
    const float* gq       = (const float*)d_in[12];
    const float* gk       = (const float*)d_in[13];

    int dim = in_sizes[5];            // 1536
    int L   = in_sizes[0] / dim;      // 5000
    int c   = in_sizes[3] / 1024;     // 64
    int dh  = 2 * c;                  // 128
    int n   = dim / dh;               // 12
    int Kp  = dim / 2;                // 768

    float *Qb, *Kb, *Vb;
    uint32_t *xp, *wp, *qp, *kp, *vp, *op;
    cudaGetSymbolAddress((void**)&Qb, g_Q);
    cudaGetSymbolAddress((void**)&Kb, g_K);
    cudaGetSymbolAddress((void**)&Vb, g_V);
    cudaGetSymbolAddress((void**)&xp, g_Xp);
    cudaGetSymbolAddress((void**)&wp, g_Wp);
    cudaGetSymbolAddress((void**)&qp, g_Qp);
    cudaGetSymbolAddress((void**)&kp, g_Kp);
    cudaGetSymbolAddress((void**)&vp, g_Vp);
    cudaGetSymbolAddress((void**)&op, g_Op);

    const size_t PLANE = (size_t)MAX_L * NPAIR;
    const size_t WSZ   = (size_t)NPAIR * DIMV;
    const size_t VPLN  = (size_t)DIMV * VROW;
    uint32_t* xp_h = xp;            uint32_t* xp_l = xp + PLANE;
    uint32_t* qp_h = qp;            uint32_t* qp_l = qp + PLANE;
    uint32_t* kp_h = kp;            uint32_t* kp_l = kp + PLANE;
    uint32_t* op_h = op;            uint32_t* op_l = op + PLANE;
    uint32_t* vp_h = vp;            uint32_t* vp_l = vp + VPLN;
    const float WS = 256.f, IWS = 1.f / 256.f;

    size_t gsmem = (size_t)(4 * 2 * 128 * G_ST) * 4;                        // 81920
    size_t asmem = (size_t)(2 * 64 * A_QP + 4 * 64 * A_QP + 4 * 128 * A_VT +
                            64 * A_PP + 64 * A_SS + 3 * 64) * 4;            // ~205KB
    cudaFuncSetAttribute(gemm_f16x3_kernel, cudaFuncAttributeMaxDynamicSharedMemorySize, (int)gsmem);
    cudaFuncSetAttribute(attn_f16x3_kernel, cudaFuncAttributeMaxDynamicSharedMemorySize, (int)asmem);

    // ---- prep: splits ----
    int npx = L * Kp;
    split_rows_kernel<<<(npx + 255) / 256, 256>>>(x, xp_h, xp_l, npx);
    {
        dim3 tg(32, 8), tgr(dim / 32, (dim + 63) / 64);
        split_trans_kernel<<<tgr, tg>>>(Wq, wp + 0 * WSZ, wp + 1 * WSZ, dim, dim, Kp, WS);
        split_trans_kernel<<<tgr, tg>>>(Wk, wp + 2 * WSZ, wp + 3 * WSZ, dim, dim, Kp, WS);
        split_trans_kernel<<<tgr, tg>>>(Wv, wp + 4 * WSZ, wp + 5 * WSZ, dim, dim, Kp, WS);
        split_trans_kernel<<<tgr, tg>>>(Wo, wp + 6 * WSZ, wp + 7 * WSZ, dim, dim, Kp, WS);
    }

    // ---- projections ----
    dim3 ggrid((L + 127) / 128, dim / 128);
    gemm_f16x3_kernel<<<ggrid, 256, gsmem>>>(xp_h, xp_l, wp + 0 * WSZ, wp + 1 * WSZ, bq, Qb, L, dim, Kp, IWS);
    gemm_f16x3_kernel<<<ggrid, 256, gsmem>>>(xp_h, xp_l, wp + 2 * WSZ, wp + 3 * WSZ, bk, Kb, L, dim, Kp, IWS);
    gemm_f16x3_kernel<<<ggrid, 256, gsmem>>>(xp_h, xp_l, wp + 4 * WSZ, wp + 5 * WSZ, bv, Vb, L, dim, Kp, IWS);

    // ---- norm + rope -> packed Q/K; transpose-split V ----
    rms_rope_split_kernel<<<L, dim / 4>>>(Qb, gq, freqs, grid_szs, qp_h, qp_l, L, dim, c);
    rms_rope_split_kernel<<<L, dim / 4>>>(Kb, gk, freqs, grid_szs, kp_h, kp_l, L, dim, c);
    {
        dim3 tg(32, 8), tgr(dim / 32, (L + 63) / 64);
        split_trans_kernel<<<tgr, tg>>>(Vb, vp_h, vp_l, L, dim, VROW, 1.f);
    }

    // ---- attention ----
    attn_f16x3_kernel<<<dim3((L + 63) / 64, n), 256, asmem>>>(
        qp_h, qp_l, kp_h, kp_l, vp_h, vp_l, op_h, op_l, seq_lens, L, n);

    // ---- output projection ----
    gemm_f16x3_kernel<<<ggrid, 256, gsmem>>>(op_h, op_l, wp + 6 * WSZ, wp + 7 * WSZ, bo, (float*)d_out, L, dim, Kp, IWS);
}

// round 15
// speedup vs baseline: 1.5765x; 1.1136x over previous
#include <cuda_runtime.h>
#include <cuda_fp16.h>
#include <math.h>
#include <stdint.h>

// ---------------------------------------------------------------------------
// WanSelfAttention: B=1, L=5000, dim=1536, heads=12, head_dim=128, fp32 I/O.
// R14: R12 structure (mma.sync fp16 error-compensated). Precision budget
// reallocated: GEMM A-operands (x, O) are plain fp16 (2 mmas/k16 instead of
// 3, no Al smem plane); weights stay hi/lo split. S = QK^T stays full x3;
// PV stays P-fp16 x V-split. tcgen05 unavailable (harness targets sm_103).
// ---------------------------------------------------------------------------

#define MAX_L 5120
#define DIMV  1536
#define NPAIR 768            // DIMV/2
#define VROW  (MAX_L / 2)    // token-pairs per d row

// fp32 intermediates
__device__ float g_Q[MAX_L * DIMV];
__device__ float g_K[MAX_L * DIMV];
__device__ float g_V[MAX_L * DIMV];
// packed fp16 buffers
__device__ uint32_t g_Xp[MAX_L * NPAIR];           // x hi: [token][kpair]
__device__ uint32_t g_Wp[8][NPAIR * DIMV];         // W transposed: [n][kpair] (hi,lo x4)
__device__ uint32_t g_Qp[2][MAX_L * NPAIR];        // [token][dpair] hi/lo
__device__ uint32_t g_Kp[2][MAX_L * NPAIR];
__device__ uint32_t g_Vp[2][DIMV * VROW];          // V transposed: [d][tokenpair] hi/lo
__device__ uint32_t g_Op[MAX_L * NPAIR];           // O hi: [token][dpair]

// ---------------- helpers ----------------
__device__ __forceinline__ void cp16(void* smem_dst, const void* gsrc) {
    uint32_t s = (uint32_t)__cvta_generic_to_shared(smem_dst);
    asm volatile("cp.async.cg.shared.global [%0], [%1], 16;\n" :: "r"(s), "l"(gsrc));
}
#define CP_COMMIT() asm volatile("cp.async.commit_group;\n" ::: "memory")
#define CP_WAIT(n)  asm volatile("cp.async.wait_group %0;\n" :: "n"(n) : "memory")

__device__ __forceinline__ void ldsm4(uint32_t* r, const uint32_t* p) {
    uint32_t a = (uint32_t)__cvta_generic_to_shared(p);
    asm volatile("ldmatrix.sync.aligned.m8n8.x4.shared.b16 {%0,%1,%2,%3}, [%4];"
        : "=r"(r[0]), "=r"(r[1]), "=r"(r[2]), "=r"(r[3]) : "r"(a));
}

__device__ __forceinline__ void split2(float x, float y, uint32_t& hi, uint32_t& lo) {
    __half2 h = __floats2half2_rn(x, y);
    float2 hf = __half22float2(h);
    __half2 l = __floats2half2_rn(x - hf.x, y - hf.y);
    hi = *reinterpret_cast<uint32_t*>(&h);
    lo = *reinterpret_cast<uint32_t*>(&l);
}

__device__ __forceinline__ void mma_f16(float* c, const uint32_t* a, const uint32_t* b) {
    asm volatile(
        "mma.sync.aligned.m16n8k16.row.col.f32.f16.f16.f32 "
        "{%0,%1,%2,%3}, {%4,%5,%6,%7}, {%8,%9}, {%0,%1,%2,%3};\n"
        : "+f"(c[0]), "+f"(c[1]), "+f"(c[2]), "+f"(c[3])
        : "r"(a[0]), "r"(a[1]), "r"(a[2]), "r"(a[3]), "r"(b[0]), "r"(b[1]));
}
__device__ __forceinline__ void mma3(float* c,
                                     const uint32_t* ah, const uint32_t* al,
                                     const uint32_t* bh, const uint32_t* bl) {
    mma_f16(c, al, bh);
    mma_f16(c, ah, bl);
    mma_f16(c, ah, bh);
}
// A exact fp16, B split hi/lo
__device__ __forceinline__ void mma2(float* c, const uint32_t* a,
                                     const uint32_t* bh, const uint32_t* bl) {
    mma_f16(c, a, bl);
    mma_f16(c, a, bh);
}

// ---------------------------------------------------------------------------
// Prep kernels
// ---------------------------------------------------------------------------
__global__ void split_rows_hi_kernel(const float* __restrict__ X,
                                     uint32_t* __restrict__ hi, int npairs)
{
    int i = blockIdx.x * 256 + threadIdx.x;
    if (i >= npairs) return;
    float2 v = reinterpret_cast<const float2*>(X)[i];
    __half2 h = __floats2half2_rn(v.x, v.y);
    hi[i] = *reinterpret_cast<uint32_t*>(&h);
}

__global__ void split_trans_kernel(const float* __restrict__ X,
                                   uint32_t* __restrict__ hi, uint32_t* __restrict__ lo,
                                   int R, int C, int RPstride, float scale)
{
    __shared__ float tile[64][33];
    int r0 = blockIdx.y * 64, c0 = blockIdx.x * 32;
    int tx = threadIdx.x, ty = threadIdx.y;   // 32 x 8
#pragma unroll
    for (int i = 0; i < 8; i++) {
        int r = r0 + ty + i * 8;
        float v = 0.f;
        if (r < R && c0 + tx < C) v = X[(size_t)r * C + c0 + tx] * scale;
        tile[ty + i * 8][tx] = v;
    }
    __syncthreads();
#pragma unroll
    for (int i = 0; i < 4; i++) {
        int cy = ty + i * 8;
        int cc = c0 + cy;
        int rp = (r0 >> 1) + tx;
        if (cc < C && 2 * rp < R) {
            uint32_t h, l;
            split2(tile[2 * tx][cy], tile[2 * tx + 1][cy], h, l);
            hi[(size_t)cc * RPstride + rp] = h;
            lo[(size_t)cc * RPstride + rp] = l;
        }
    }
}

// ---------------------------------------------------------------------------
// GEMM: C[M,N] = (A_fp16 @ Bp^T_split) * outScale + bias
// A: [M][Kp] fp16 pairs K-major (hi only). Bp: [N][Kp] pairs (hi/lo).
// BM=128 BN=128 BKP=16 pairs (K=32), 256 thr, warps 2x4, warp tile 64x32.
// ---------------------------------------------------------------------------
#define G_ST 20
__global__ void __launch_bounds__(256)
gemm_f16_kernel(const uint32_t* __restrict__ Ahi,
                const uint32_t* __restrict__ Bhi, const uint32_t* __restrict__ Blo,
                const float* __restrict__ bias, float* __restrict__ C,
                int M, int N, int Kp, float outScale)
{
    const int TBUF = 128 * G_ST;
    extern __shared__ uint32_t sh[];
    uint32_t* Ah = sh;                     // 2*TBUF
    uint32_t* Bh = Ah + 2 * TBUF;          // 2*TBUF
    uint32_t* Bl = Bh + 2 * TBUF;          // 2*TBUF

    int tid = threadIdx.x;
    int lane = tid & 31, warp = tid >> 5;
    int wm = warp >> 2, wn = warp & 3;
    int g = lane >> 2, tg = lane & 3;
    int row0 = blockIdx.x * 128, col0 = blockIdx.y * 128;

    int arow  = (lane & 7) + ((lane & 8) ? 8 : 0);
    int apair = (lane & 16) ? 4 : 0;
    int brow  = (lane & 7) + ((lane & 16) ? 8 : 0);
    int bpair = (lane & 8) ? 4 : 0;

    float acc[4][4][4];
#pragma unroll
    for (int mt = 0; mt < 4; mt++)
#pragma unroll
        for (int nt = 0; nt < 4; nt++)
#pragma unroll
            for (int r = 0; r < 4; r++) acc[mt][nt][r] = 0.f;

    auto issue = [&](int ktp, int buf) {
#pragma unroll
        for (int i = 0; i < 2; i++) {
            int idx = tid + i * 256;
            int r = idx >> 2, pc = (idx & 3) << 2;
            int gr = row0 + r; if (gr >= M) gr = M - 1;
            cp16(Ah + buf * TBUF + r * G_ST + pc, Ahi + (size_t)gr * Kp + ktp + pc);
        }
#pragma unroll
        for (int i = 0; i < 2; i++) {
            int idx = tid + i * 256;
            int r = idx >> 2, pc = (idx & 3) << 2;
            size_t go = (size_t)(col0 + r) * Kp + ktp + pc;
            cp16(Bh + buf * TBUF + r * G_ST + pc, Bhi + go);
            cp16(Bl + buf * TBUF + r * G_ST + pc, Blo + go);
        }
    };

    issue(0, 0); CP_COMMIT();
    int nk = Kp / 16;
    for (int t = 0; t < nk; t++) {
        int buf = t & 1;
        if (t + 1 < nk) { issue((t + 1) * 16, buf ^ 1); CP_COMMIT(); CP_WAIT(1); }
        else           { CP_WAIT(0); }
        __syncthreads();

        const uint32_t* Abh = Ah + buf * TBUF;
        const uint32_t* Bbh = Bh + buf * TBUF;
        const uint32_t* Bbl = Bl + buf * TBUF;
#pragma unroll
        for (int ks = 0; ks < 2; ks++) {
            int pb = ks * 8;
            uint32_t ah[4][4], bh2[2][4], bl2[2][4];
#pragma unroll
            for (int mt = 0; mt < 4; mt++) {
                int ro = (wm * 64 + mt * 16 + arow) * G_ST + apair + pb;
                ldsm4(ah[mt], Abh + ro);
            }
#pragma unroll
            for (int nt2 = 0; nt2 < 2; nt2++) {
                int ro = (wn * 32 + nt2 * 16 + brow) * G_ST + bpair + pb;
                ldsm4(bh2[nt2], Bbh + ro);
                ldsm4(bl2[nt2], Bbl + ro);
            }
#pragma unroll
            for (int mt = 0; mt < 4; mt++)
#pragma unroll
                for (int nt = 0; nt < 4; nt++) {
                    const uint32_t* bhp = &bh2[nt >> 1][(nt & 1) * 2];
                    const uint32_t* blp = &bl2[nt >> 1][(nt & 1) * 2];
                    mma2(acc[mt][nt], ah[mt], bhp, blp);
                }
        }
        __syncthreads();
    }

#pragma unroll
    for (int mt = 0; mt < 4; mt++) {
#pragma unroll
        for (int nt = 0; nt < 4; nt++) {
            int col = col0 + wn * 32 + nt * 8 + 2 * tg;
            float2 b2 = *(const float2*)&bias[col];
            int r0 = row0 + wm * 64 + mt * 16 + g;
            if (r0 < M) {
                float2 o = { acc[mt][nt][0] * outScale + b2.x, acc[mt][nt][1] * outScale + b2.y };
                *(float2*)&C[(size_t)r0 * N + col] = o;
            }
            int r1 = r0 + 8;
            if (r1 < M) {
                float2 o = { acc[mt][nt][2] * outScale + b2.x, acc[mt][nt][3] * outScale + b2.y };
                *(float2*)&C[(size_t)r1 * N + col] = o;
            }
        }
    }
}

// ---------------------------------------------------------------------------
// Fused RMSNorm + RoPE -> packed fp16 hi/lo pairs
// ---------------------------------------------------------------------------
__global__ void rms_rope_split_kernel(const float* __restrict__ Y,
                                      const float* __restrict__ g,
                                      const float* __restrict__ freqs,
                                      const int* __restrict__ grid_sizes,
                                      uint32_t* __restrict__ ohi, uint32_t* __restrict__ olo,
                                      int L, int dim, int c)
{
    int t = blockIdx.x;
    int tid = threadIdx.x;
    const float* row = Y + (size_t)t * dim;

    float4 v = *reinterpret_cast<const float4*>(&row[4 * tid]);
    float ss = v.x * v.x + v.y * v.y + v.z * v.z + v.w * v.w;

    __shared__ float red[32];
#pragma unroll
    for (int o = 16; o > 0; o >>= 1) ss += __shfl_xor_sync(0xffffffffu, ss, o);
    int warp = tid >> 5, lane = tid & 31;
    int nwarps = blockDim.x >> 5;
    if (lane == 0) red[warp] = ss;
    __syncthreads();
    __shared__ float s_inv;
    if (tid == 0) {
        float tot = 0.f;
        for (int i = 0; i < nwarps; i++) tot += red[i];
        s_inv = rsqrtf(tot / (float)dim + 1e-6f);
    }
    __syncthreads();
    float inv = s_inv;

    float4 gg = *reinterpret_cast<const float4*>(&g[4 * tid]);
    v.x *= inv * gg.x; v.y *= inv * gg.y; v.z *= inv * gg.z; v.w *= inv * gg.w;

    int gf = grid_sizes[0], gh = grid_sizes[1], gw = grid_sizes[2];
    int hw = gh * gw;
    int sl = gf * hw;
    if (t < sl) {
        int fi = t / hw;
        int rem = t - fi * hw;
        int hi2 = rem / gw;
        int wi = rem - hi2 * gw;
        int c1 = c / 3;
        int c0 = c - 2 * c1;
#pragma unroll
        for (int pp = 0; pp < 2; pp++) {
            int p = 2 * tid + pp;
            int j = p % c;
            int idx = (j < c0) ? fi : ((j < c0 + c1) ? hi2 : wi);
            float ang = freqs[(size_t)idx * c + j];
            float sn, cs;
            sincosf(ang, &sn, &cs);
            float re = (pp == 0) ? v.x : v.z;
            float im = (pp == 0) ? v.y : v.w;
            float re2 = re * cs - im * sn;
            float im2 = re * sn + im * cs;
            if (pp == 0) { v.x = re2; v.y = im2; }
            else         { v.z = re2; v.w = im2; }
        }
    }
    size_t pbase = (size_t)t * (dim / 2) + 2 * tid;
    uint32_t h0, l0, h1, l1;
    split2(v.x, v.y, h0, l0);
    split2(v.z, v.w, h1, l1);
    ohi[pbase] = h0; olo[pbase] = l0;
    ohi[pbase + 1] = h1; olo[pbase + 1] = l1;
}

// ---------------------------------------------------------------------------
// Flash attention (R12). 64q x 64k tiles, d=128 (64 pairs). 256 thr.
// S: fp16x3. PV: fp16 P x split V. Output stored as fp16 hi only.
// ---------------------------------------------------------------------------
#define A_QP 68
#define A_VT 36
#define A_PP 36
#define A_SS 68
__global__ void __launch_bounds__(256, 1)
attn_f16x3_kernel(const uint32_t* __restrict__ Qhi, const uint32_t* __restrict__ Qlo,
                  const uint32_t* __restrict__ Khi, const uint32_t* __restrict__ Klo,
                  const uint32_t* __restrict__ Vhi, const uint32_t* __restrict__ Vlo,
                  uint32_t* __restrict__ Ohi,
                  const int* __restrict__ seq_lens, int L, int nheads)
{
    const int QTS = 64 * A_QP;
    const int VTS = 128 * A_VT;
    extern __shared__ uint32_t sh[];
    uint32_t* Qh = sh;
    uint32_t* Ql = Qh + QTS;
    uint32_t* Kh = Ql + QTS;
    uint32_t* Kl = Kh + 2 * QTS;
    uint32_t* Vh = Kl + 2 * QTS;
    uint32_t* Vl = Vh + 2 * VTS;
    uint32_t* Ph = Vl + 2 * VTS;
    float*    Ps = (float*)(Ph + 64 * A_PP);
    float*    s_m = Ps + 64 * A_SS;
    float*    s_l = s_m + 64;
    float*    s_c = s_l + 64;

    int hd = blockIdx.y;
    int q0 = blockIdx.x * 64;
    int tid = threadIdx.x, lane = tid & 31, warp = tid >> 5;
    int wm = warp >> 2, wn = warp & 3;
    int g = lane >> 2, tg = lane & 3;
    int seqlen = seq_lens[0]; if (seqlen > L) seqlen = L;
    const float scale = rsqrtf(128.f);
    const int hq = hd * 64;
    const int hv = hd * 128;

    int marow  = (lane & 7) + ((lane & 8) ? 8 : 0);
    int mapair = (lane & 16) ? 4 : 0;
    int nbrow  = (lane & 7) + ((lane & 16) ? 8 : 0);
    int nbpair = (lane & 8) ? 4 : 0;

#pragma unroll
    for (int i = 0; i < 4; i++) {
        int idx = tid + i * 256;
        int r = idx >> 4, pc = (idx & 15) << 2;
        int gr = q0 + r; if (gr >= L) gr = L - 1;
        size_t go = (size_t)gr * NPAIR + hq + pc;
        cp16(Qh + r * A_QP + pc, Qhi + go);
        cp16(Ql + r * A_QP + pc, Qlo + go);
    }
    auto issueKV = [&](int k0, int buf) {
#pragma unroll
        for (int i = 0; i < 4; i++) {
            int idx = tid + i * 256;
            int r = idx >> 4, pc = (idx & 15) << 2;
            int gr = k0 + r; if (gr >= seqlen) gr = seqlen - 1;
            size_t go = (size_t)gr * NPAIR + hq + pc;
            cp16(Kh + buf * QTS + r * A_QP + pc, Khi + go);
            cp16(Kl + buf * QTS + r * A_QP + pc, Klo + go);
        }
        int tkp0 = k0 >> 1;
#pragma unroll
        for (int i = 0; i < 4; i++) {
            int idx = tid + i * 256;
            int r = idx >> 3, pc = (idx & 7) << 2;
            size_t go = (size_t)(hv + r) * VROW + tkp0 + pc;
            cp16(Vh + buf * VTS + r * A_VT + pc, Vhi + go);
            cp16(Vl + buf * VTS + r * A_VT + pc, Vlo + go);
        }
    };
    issueKV(0, 0); CP_COMMIT();

    if (tid < 64) { s_m[tid] = -1e30f; s_l[tid] = 0.f; }

    float acc_o[2][4][4];
#pragma unroll
    for (int mt = 0; mt < 2; mt++)
#pragma unroll
        for (int nt = 0; nt < 4; nt++)
#pragma unroll
            for (int r = 0; r < 4; r++) acc_o[mt][nt][r] = 0.f;

    int nkt = (seqlen + 63) >> 6;
    for (int t = 0; t < nkt; t++) {
        int buf = t & 1;
        if (t + 1 < nkt) { issueKV((t + 1) * 64, buf ^ 1); CP_COMMIT(); CP_WAIT(1); }
        else            { CP_WAIT(0); }
        __syncthreads();

        const uint32_t* Kbh = Kh + buf * QTS;
        const uint32_t* Kbl = Kl + buf * QTS;
        float acc_s[2][2][4];
#pragma unroll
        for (int mt = 0; mt < 2; mt++)
#pragma unroll
            for (int nt = 0; nt < 2; nt++)
#pragma unroll
                for (int r = 0; r < 4; r++) acc_s[mt][nt][r] = 0.f;

#pragma unroll
        for (int ks = 0; ks < 8; ks++) {
            int pb = ks * 8;
            uint32_t ah[2][4], al[2][4], bh2[4], bl2[4];
#pragma unroll
            for (int mt = 0; mt < 2; mt++) {
                int ro = (wm * 32 + mt * 16 + marow) * A_QP + mapair + pb;
                ldsm4(ah[mt], Qh + ro);
                ldsm4(al[mt], Ql + ro);
            }
            {
                int ro = (wn * 16 + nbrow) * A_QP + nbpair + pb;
                ldsm4(bh2, Kbh + ro);
                ldsm4(bl2, Kbl + ro);
            }
#pragma unroll
            for (int mt = 0; mt < 2; mt++)
#pragma unroll
                for (int nt = 0; nt < 2; nt++)
                    mma3(acc_s[mt][nt], ah[mt], al[mt], &bh2[nt * 2], &bl2[nt * 2]);
        }
#pragma unroll
        for (int mt = 0; mt < 2; mt++) {
            int r0 = wm * 32 + mt * 16 + g;
#pragma unroll
            for (int nt = 0; nt < 2; nt++) {
                int cc = wn * 16 + nt * 8 + 2 * tg;
                *(float2*)&Ps[r0 * A_SS + cc]       = make_float2(acc_s[mt][nt][0], acc_s[mt][nt][1]);
                *(float2*)&Ps[(r0 + 8) * A_SS + cc] = make_float2(acc_s[mt][nt][2], acc_s[mt][nt][3]);
            }
        }
        __syncthreads();

        {
            int row = tid >> 2, sub = tid & 3;
            int k0 = t * 64;
            const float* pr = Ps + row * A_SS + sub * 16;
            float vals[16];
            float mx = -1e30f;
#pragma unroll
            for (int j = 0; j < 16; j++) {
                int col = sub * 16 + j;
                float vv = (k0 + col < seqlen) ? pr[j] * scale : -1e30f;
                vals[j] = vv;
                mx = fmaxf(mx, vv);
            }
            mx = fmaxf(mx, __shfl_xor_sync(0xffffffffu, mx, 1));
            mx = fmaxf(mx, __shfl_xor_sync(0xffffffffu, mx, 2));
            float mold = s_m[row];
            float mnew = fmaxf(mold, mx);
            float ls = 0.f;
#pragma unroll
            for (int j = 0; j < 16; j++) {
                vals[j] = __expf(vals[j] - mnew);
                ls += vals[j];
            }
#pragma unroll
            for (int jp = 0; jp < 8; jp++) {
                __half2 hh = __floats2half2_rn(vals[2 * jp], vals[2 * jp + 1]);
                Ph[row * A_PP + sub * 8 + jp] = *reinterpret_cast<uint32_t*>(&hh);
            }
            ls += __shfl_xor_sync(0xffffffffu, ls, 1);
            ls += __shfl_xor_sync(0xffffffffu, ls, 2);
            if (sub == 0) {
                float cf = __expf(mold - mnew);
                s_m[row] = mnew;
                s_l[row] = s_l[row] * cf + ls;
                s_c[row] = cf;
            }
        }
        __syncthreads();

        const uint32_t* Vbh = Vh + buf * VTS;
        const uint32_t* Vbl = Vl + buf * VTS;
#pragma unroll
        for (int mt = 0; mt < 2; mt++) {
            int r0 = wm * 32 + mt * 16 + g;
            float cf0 = s_c[r0], cf1 = s_c[r0 + 8];
#pragma unroll
            for (int nt = 0; nt < 4; nt++) {
                acc_o[mt][nt][0] *= cf0; acc_o[mt][nt][1] *= cf0;
                acc_o[mt][nt][2] *= cf1; acc_o[mt][nt][3] *= cf1;
            }
        }
#pragma unroll
        for (int ks = 0; ks < 4; ks++) {
            int pb = ks * 8;
            uint32_t ah[2][4], bh2[2][4], bl2[2][4];
#pragma unroll
            for (int mt = 0; mt < 2; mt++) {
                int ro = (wm * 32 + mt * 16 + marow) * A_PP + mapair + pb;
                ldsm4(ah[mt], Ph + ro);
            }
#pragma unroll
            for (int nt2 = 0; nt2 < 2; nt2++) {
                int ro = (wn * 32 + nt2 * 16 + nbrow) * A_VT + nbpair + pb;
                ldsm4(bh2[nt2], Vbh + ro);
                ldsm4(bl2[nt2], Vbl + ro);
            }
#pragma unroll
            for (int mt = 0; mt < 2; mt++)
#pragma unroll
                for (int nt = 0; nt < 4; nt++) {
                    const uint32_t* bhp = &bh2[nt >> 1][(nt & 1) * 2];
                    const uint32_t* blp = &bl2[nt >> 1][(nt & 1) * 2];
                    mma2(acc_o[mt][nt], ah[mt], bhp, blp);
                }
        }
        __syncthreads();
    }

    // ---- epilogue: normalize + store fp16 hi pairs ----
#pragma unroll
    for (int mt = 0; mt < 2; mt++) {
        int r0 = wm * 32 + mt * 16 + g;
        float il0 = 1.f / s_l[r0];
        float il1 = 1.f / s_l[r0 + 8];
#pragma unroll
        for (int nt = 0; nt < 4; nt++) {
            int pidx = wn * 16 + nt * 4 + tg;
            int gr0 = q0 + r0;
            if (gr0 < L) {
                __half2 hh = __floats2half2_rn(acc_o[mt][nt][0] * il0, acc_o[mt][nt][1] * il0);
                Ohi[(size_t)gr0 * NPAIR + hq + pidx] = *reinterpret_cast<uint32_t*>(&hh);
            }
            int gr1 = gr0 + 8;
            if (gr1 < L) {
                __half2 hh = __floats2half2_rn(acc_o[mt][nt][2] * il1, acc_o[mt][nt][3] * il1);
                Ohi[(size_t)gr1 * NPAIR + hq + pidx] = *reinterpret_cast<uint32_t*>(&hh);
            }
        }
    }
}

// ---------------------------------------------------------------------------
// Host launcher
// ---------------------------------------------------------------------------
extern "C" void kernel_launch(void* const* d_in, const int* in_sizes, int n_in,
                              void* d_out, int out_size)
{
    const float* x        = (const float*)d_in[0];
    const int*   seq_lens = (const int*)  d_in[1];
    const int*   grid_szs = (const int*)  d_in[2];
    const float* freqs    = (const float*)d_in[3];
    const float* Wq       = (const float*)d_in[4];
    const float* bq       = (const float*)d_in[5];
    const float* Wk       = (const float*)d_in[6];
    const float* bk       = (const float*)d_in[7];
    const float* Wv       = (const float*)d_in[8];
    const float* bv       = (const float*)d_in[9];
    const float* Wo       = (const float*)d_in[10];
    const float* bo       = (const float*)d_in[11];
    const float* gq       = (const float*)d_in[12];
    const float* gk       = (const float*)d_in[13];

    int dim = in_sizes[5];            // 1536
    int L   = in_sizes[0] / dim;      // 5000
    int c   = in_sizes[3] / 1024;     // 64
    int dh  = 2 * c;                  // 128
    int n   = dim / dh;               // 12
    int Kp  = dim / 2;                // 768

    float *Qb, *Kb, *Vb;
    uint32_t *xp, *wp, *qp, *kp, *vp, *op;
    cudaGetSymbolAddress((void**)&Qb, g_Q);
    cudaGetSymbolAddress((void**)&Kb, g_K);
    cudaGetSymbolAddress((void**)&Vb, g_V);
    cudaGetSymbolAddress((void**)&xp, g_Xp);
    cudaGetSymbolAddress((void**)&wp, g_Wp);
    cudaGetSymbolAddress((void**)&qp, g_Qp);
    cudaGetSymbolAddress((void**)&kp, g_Kp);
    cudaGetSymbolAddress((void**)&vp, g_Vp);
    cudaGetSymbolAddress((void**)&op, g_Op);

    const size_t PLANE = (size_t)MAX_L * NPAIR;
    const size_t WSZ   = (size_t)NPAIR * DIMV;
    const size_t VPLN  = (size_t)DIMV * VROW;
    uint32_t* qp_h = qp;            uint32_t* qp_l = qp + PLANE;
    uint32_t* kp_h = kp;            uint32_t* kp_l = kp + PLANE;
    uint32_t* vp_h = vp;            uint32_t* vp_l = vp + VPLN;
    const float WS = 256.f, IWS = 1.f / 256.f;

    size_t gsmem = (size_t)(3 * 2 * 128 * G_ST) * 4;                        // 61440
    size_t asmem = (size_t)(2 * 64 * A_QP + 4 * 64 * A_QP + 4 * 128 * A_VT +
                            64 * A_PP + 64 * A_SS + 3 * 64) * 4;
    cudaFuncSetAttribute(gemm_f16_kernel, cudaFuncAttributeMaxDynamicSharedMemorySize, (int)gsmem);
    cudaFuncSetAttribute(attn_f16x3_kernel, cudaFuncAttributeMaxDynamicSharedMemorySize, (int)asmem);

    // ---- prep: splits ----
    int npx = L * Kp;
    split_rows_hi_kernel<<<(npx + 255) / 256, 256>>>(x, xp, npx);
    {
        dim3 tg(32, 8), tgr(dim / 32, (dim + 63) / 64);
        split_trans_kernel<<<tgr, tg>>>(Wq, wp + 0 * WSZ, wp + 1 * WSZ, dim, dim, Kp, WS);
        split_trans_kernel<<<tgr, tg>>>(Wk, wp + 2 * WSZ, wp + 3 * WSZ, dim, dim, Kp, WS);
        split_trans_kernel<<<tgr, tg>>>(Wv, wp + 4 * WSZ, wp + 5 * WSZ, dim, dim, Kp, WS);
        split_trans_kernel<<<tgr, tg>>>(Wo, wp + 6 * WSZ, wp + 7 * WSZ, dim, dim, Kp, WS);
    }

    // ---- projections (A = x fp16 hi) ----
    dim3 ggrid((L + 127) / 128, dim / 128);
    gemm_f16_kernel<<<ggrid, 256, gsmem>>>(xp, wp + 0 * WSZ, wp + 1 * WSZ, bq, Qb, L, dim, Kp, IWS);
    gemm_f16_kernel<<<ggrid, 256, gsmem>>>(xp, wp + 2 * WSZ, wp + 3 * WSZ, bk, Kb, L, dim, Kp, IWS);
    gemm_f16_kernel<<<ggrid, 256, gsmem>>>(xp, wp + 4 * WSZ, wp + 5 * WSZ, bv, Vb, L, dim, Kp, IWS);

    // ---- norm + rope -> packed Q/K; transpose-split V ----
    rms_rope_split_kernel<<<L, dim / 4>>>(Qb, gq, freqs, grid_szs, qp_h, qp_l, L, dim, c);
    rms_rope_split_kernel<<<L, dim / 4>>>(Kb, gk, freqs, grid_szs, kp_h, kp_l, L, dim, c);
    {
        dim3 tg(32, 8), tgr(dim / 32, (L + 63) / 64);
        split_trans_kernel<<<tgr, tg>>>(Vb, vp_h, vp_l, L, dim, VROW, 1.f);
    }

    // ---- attention (O stored fp16 hi) ----
    attn_f16x3_kernel<<<dim3((L + 63) / 64, n), 256, asmem>>>(
        qp_h, qp_l, kp_h, kp_l, vp_h, vp_l, op, seq_lens, L, n);

    // ---- output projection (A = O fp16 hi) ----
    gemm_f16_kernel<<<ggrid, 256, gsmem>>>(op, wp + 6 * WSZ, wp + 7 * WSZ, bo, (float*)d_out, L, dim, Kp, IWS);
}